// round 14
// baseline (speedup 1.0000x reference)
#include <cuda_runtime.h>
#include <cuda_bf16.h>
#include <cstdint>

#define D 128
#define MAXN 100000
#define CAP3 48         // per-type bucket capacity (Poisson(5): P(>=48) ~ 1e-30)

// ---------------- device scratch (allocation-free) ---------------------------
// g_Wfrag[type][kstep(8)][ntile(16)][lane(32)] : uint4 = {b0_hi, b1_hi, b0_lo, b1_lo}
__device__ __align__(16) uint4 g_Wfrag[3][8][16][32];
__device__ float g_Q[3][(size_t)MAXN * D];
// per-type destination buckets: type0 AB->B dsts, type1 BA->A, type2 AA->A
__device__ int g_cnt3[3][MAXN];
__device__ unsigned g_bkt3[3][(size_t)MAXN * CAP3];

// ---------------- mma.sync helper (sm_80+ path, legal on target sm_103) ------
__device__ __forceinline__ void mma_bf16(float* c, uint32_t a0, uint32_t a1,
                                         uint32_t a2, uint32_t a3,
                                         uint32_t b0, uint32_t b1) {
    asm volatile(
        "mma.sync.aligned.m16n8k16.row.col.f32.bf16.bf16.f32 "
        "{%0,%1,%2,%3}, {%4,%5,%6,%7}, {%8,%9}, {%0,%1,%2,%3};"
        : "+f"(c[0]), "+f"(c[1]), "+f"(c[2]), "+f"(c[3])
        : "r"(a0), "r"(a1), "r"(a2), "r"(a3), "r"(b0), "r"(b1));
}

// ---------------- kernel 0: W = W_pos - softplus(W_negraw), split + frag-pack -
__global__ void compute_W_kernel(const float* __restrict__ wp0, const float* __restrict__ wn0,
                                 const float* __restrict__ wp1, const float* __restrict__ wn1,
                                 const float* __restrict__ wp2, const float* __restrict__ wn2) {
    int i = blockIdx.x * blockDim.x + threadIdx.x;
    if (i >= 3 * D * D) return;
    int ty = i / (D * D), r = i % (D * D);
    int k = r / D, n = r % D;
    const float* wp = (ty == 0) ? wp0 : (ty == 1 ? wp1 : wp2);
    const float* wn = (ty == 0) ? wn0 : (ty == 1 ? wn1 : wn2);
    float x = wn[r];
    float sp = fmaxf(x, 0.0f) + log1pf(expf(-fabsf(x)));
    float w = wp[r] - sp;
    __nv_bfloat16 hb = __float2bfloat16(w);
    __nv_bfloat16 lb = __float2bfloat16(w - __bfloat162float(hb));

    int s  = k >> 4;
    int kk = k & 15;
    int reg  = kk >> 3;
    int tq   = (kk >> 1) & 3;
    int half = kk & 1;
    int j    = n >> 3;
    int lane = (n & 7) * 4 + tq;

    unsigned char* slot = (unsigned char*)&g_Wfrag[ty][s][j][lane];
    *(__nv_bfloat16*)(slot + 0 + reg * 4 + half * 2) = hb;
    *(__nv_bfloat16*)(slot + 8 + reg * 4 + half * 2) = lb;
}

// ---------------- kernel 1: zero destination counts --------------------------
__global__ void zero_cnt_kernel() {
    int i = blockIdx.x * blockDim.x + threadIdx.x;
    if (i < 3 * MAXN) (&g_cnt3[0][0])[i] = 0;
}

// ---------------- kernel 2: fused softmax + split-bf16 HMMA GEMM -------------
// Block = 256 threads (8 warps), 64 rows/CTA; warp -> (mtile, N-half).
// W fragments staged through an 8KB smem buffer per k-step (cooperative
// LDG->STS, register-prefetch of next step overlapped with MMAs).
// Static smem: P 34KB + Wbuf 8KB = 42KB -> 3 CTAs/SM.  (R10-proven config.)
#define PROW 136

__global__ void __launch_bounds__(256, 3)
hmma_gemm_kernel(const float* __restrict__ X, int nrows, int t0, int t1) {
    __shared__ __align__(16) __nv_bfloat16 sph[64 * PROW];
    __shared__ __align__(16) __nv_bfloat16 spl[64 * PROW];
    __shared__ __align__(16) uint4 sWb[512];          // 16 j x 32 lanes, one k-step

    const int tid  = threadIdx.x;
    const int lane = tid & 31;
    const int warp = tid >> 5;
    const int row0 = blockIdx.x * 64;

    // ---- softmax: 8 warps x 8 rows each; lane owns 4 cols of its row
    #pragma unroll
    for (int r = 0; r < 8; r++) {
        int lrow = warp * 8 + r;
        int row  = row0 + lrow;
        if (row < nrows) {
            const float* xr = X + (size_t)row * D;
            float v[4];
            #pragma unroll
            for (int q = 0; q < 4; q++) v[q] = xr[lane + 32 * q];
            float m = fmaxf(fmaxf(v[0], v[1]), fmaxf(v[2], v[3]));
            #pragma unroll
            for (int o = 16; o > 0; o >>= 1) m = fmaxf(m, __shfl_xor_sync(0xffffffffu, m, o));
            float s = 0.f;
            #pragma unroll
            for (int q = 0; q < 4; q++) { v[q] = expf(v[q] - m); s += v[q]; }
            #pragma unroll
            for (int o = 16; o > 0; o >>= 1) s += __shfl_xor_sync(0xffffffffu, s, o);
            float inv = 1.0f / s;
            #pragma unroll
            for (int q = 0; q < 4; q++) {
                float p = v[q] * inv;
                __nv_bfloat16 hb = __float2bfloat16(p);
                __nv_bfloat16 lb = __float2bfloat16(p - __bfloat162float(hb));
                int col = lane + 32 * q;
                sph[lrow * PROW + col] = hb;
                spl[lrow * PROW + col] = lb;
            }
        } else {
            __nv_bfloat16 z = __float2bfloat16(0.f);
            #pragma unroll
            for (int q = 0; q < 4; q++) {
                int col = lane + 32 * q;
                sph[lrow * PROW + col] = z;
                spl[lrow * PROW + col] = z;
            }
        }
    }
    __syncthreads();

    const int mt = warp >> 1;
    const int nh = warp & 1;
    const int g  = lane >> 2;
    const int tq = lane & 3;

    const uint32_t* ph32 = (const uint32_t*)sph;
    const uint32_t* pl32 = (const uint32_t*)spl;
    const int rbase = (mt * 16 + g) * (PROW / 2);
    const uint4* bs = &sWb[(8 * nh) * 32 + lane];

    const int ntypes = (t1 >= 0) ? 2 : 1;
    for (int tt = 0; tt < ntypes; tt++) {
        const int ty = tt ? t1 : t0;
        const uint4* wt = &g_Wfrag[ty][0][0][0];

        float acc[32];
        #pragma unroll
        for (int i = 0; i < 32; i++) acc[i] = 0.f;

        // prefetch k-step 0 (2 x LDG.128 per thread; 8KB block is contiguous)
        uint4 p0 = wt[tid], p1 = wt[tid + 256];

        #pragma unroll
        for (int s = 0; s < 8; s++) {
            // stage current k-step into smem
            sWb[tid] = p0;
            sWb[tid + 256] = p1;
            __syncthreads();
            // prefetch next k-step; LDG latency hides under the 24 MMAs below
            if (s < 7) { p0 = wt[(s + 1) * 512 + tid]; p1 = wt[(s + 1) * 512 + tid + 256]; }

            const int o = rbase + 8 * s + tq;
            uint32_t ah0 = ph32[o],           ah2 = ph32[o + 4];
            uint32_t ah1 = ph32[o + 8 * 68],  ah3 = ph32[o + 4 + 8 * 68];
            uint32_t al0 = pl32[o],           al2 = pl32[o + 4];
            uint32_t al1 = pl32[o + 8 * 68],  al3 = pl32[o + 4 + 8 * 68];
            #pragma unroll
            for (int j = 0; j < 8; j++) {
                uint4 b = bs[j * 32];                      // LDS.128, conflict-free
                mma_bf16(acc + 4 * j, ah0, ah1, ah2, ah3, b.x, b.y);   // Ph @ Wh
                mma_bf16(acc + 4 * j, al0, al1, al2, al3, b.x, b.y);   // Pl @ Wh
                mma_bf16(acc + 4 * j, ah0, ah1, ah2, ah3, b.z, b.w);   // Ph @ Wl
            }
            __syncthreads();   // all reads of sWb done before next store
        }

        float* Q = g_Q[ty];
        const int rowa = row0 + mt * 16 + g;
        const int rowb = rowa + 8;
        #pragma unroll
        for (int j = 0; j < 8; j++) {
            int cn = 64 * nh + 8 * j + 2 * tq;
            if (rowa < nrows)
                *(float2*)(Q + (size_t)rowa * D + cn) = make_float2(acc[4 * j], acc[4 * j + 1]);
            if (rowb < nrows)
                *(float2*)(Q + (size_t)rowb * D + cn) = make_float2(acc[4 * j + 2], acc[4 * j + 3]);
        }
    }
}

// ---------------- kernel 3: edge placement into per-type buckets -------------
__global__ void place_kernel(const int* __restrict__ e0, int E0,   // AB: dst B
                             const int* __restrict__ e1, int E1,   // BA: dst A
                             const int* __restrict__ e2, int E2) { // AA: dst A
    int i = blockIdx.x * blockDim.x + threadIdx.x;
    int stride = gridDim.x * blockDim.x;
    int ET = E0 + E1 + E2;
    for (int e = i; e < ET; e += stride) {
        int src, dst, q;
        if (e < E0)            { src = e0[e];          dst = e0[E0 + e];          q = 0; }
        else if (e < E0 + E1)  { int le = e - E0;      src = e1[le]; dst = e1[E1 + le]; q = 1; }
        else                   { int le = e - E0 - E1; src = e2[le]; dst = e2[E2 + le]; q = 2; }
        int pos = atomicAdd(&g_cnt3[q][dst], 1);
        if (pos < CAP3) g_bkt3[q][(size_t)dst * CAP3 + pos] = (unsigned)src;
    }
}

// ---------------- kernel 4: per-dst gather + register accumulate -------------
// warp per destination row; ACCUM: 0 = overwrite out, 1 = out += sum.
template <int QI, int ACCUM>
__global__ void __launch_bounds__(256)
gather_kernel(float* __restrict__ out, int ndst) {
    int dw   = (blockIdx.x * blockDim.x + threadIdx.x) >> 5;
    int lane = threadIdx.x & 31;
    if (dw >= ndst) return;

    int cnt = min(g_cnt3[QI][dw], CAP3);
    const unsigned* bk = &g_bkt3[QI][(size_t)dw * CAP3];
    const float* Q = g_Q[QI];

    float4 acc;
    float4* op = (float4*)(out + (size_t)dw * D) + lane;
    if (ACCUM) acc = *op;
    else       acc = make_float4(0.f, 0.f, 0.f, 0.f);

    int n1 = min(cnt, 32);
    unsigned pk = (lane < n1) ? bk[lane] : 0u;
    for (int e = 0; e < n1; e++) {
        unsigned p = __shfl_sync(0xffffffffu, pk, e);
        float4 v = __ldg((const float4*)(Q + (size_t)p * D) + lane);
        acc.x += v.x; acc.y += v.y; acc.z += v.z; acc.w += v.w;
    }
    if (cnt > 32) {
        int n2 = cnt - 32;
        unsigned pk2 = (lane < n2) ? bk[32 + lane] : 0u;
        for (int e = 0; e < n2; e++) {
            unsigned p = __shfl_sync(0xffffffffu, pk2, e);
            float4 v = __ldg((const float4*)(Q + (size_t)p * D) + lane);
            acc.x += v.x; acc.y += v.y; acc.z += v.z; acc.w += v.w;
        }
    }

    *op = acc;
}

// ---------------- launch -----------------------------------------------------
// Schedule (GEMMs serialized; GEMM ∥ gather only):
//   s0: W -> GEMM-A(Q0,Q2) -> [wait place] gather-B(Q0,write dB)
//       -> gather-A2(Q2,write dA) -> [wait GEMM-B] gather-A1(Q1,accum dA)
//   s2: [fork] zero_cnt -> place ; [wait GEMM-A] GEMM-B(Q1)
extern "C" void kernel_launch(void* const* d_in, const int* in_sizes, int n_in,
                              void* d_out, int out_size) {
    const float* logits_A = (const float*)d_in[0];
    const float* logits_B = (const float*)d_in[1];
    const int* e_AB = (const int*)d_in[4];
    const int* e_BA = (const int*)d_in[5];
    const int* e_AA = (const int*)d_in[6];
    const float* Wp_AB = (const float*)d_in[7],  *Wn_AB = (const float*)d_in[8];
    const float* Wp_BA = (const float*)d_in[9],  *Wn_BA = (const float*)d_in[10];
    const float* Wp_AA = (const float*)d_in[11], *Wn_AA = (const float*)d_in[12];
    float* out = (float*)d_out;

    const int NA = in_sizes[0] / D;
    const int NB = in_sizes[1] / D;
    const int E_AB = in_sizes[4] / 2;
    const int E_BA = in_sizes[5] / 2;
    const int E_AA = in_sizes[6] / 2;
    const int ET = E_AB + E_BA + E_AA;

    static cudaStream_t s2 = nullptr;
    static cudaEvent_t evFork = nullptr, evPlace = nullptr, evQA = nullptr, evB = nullptr;
    if (s2 == nullptr) {
        cudaStreamCreateWithFlags(&s2, cudaStreamNonBlocking);
        cudaEventCreateWithFlags(&evFork, cudaEventDisableTiming);
        cudaEventCreateWithFlags(&evPlace, cudaEventDisableTiming);
        cudaEventCreateWithFlags(&evQA, cudaEventDisableTiming);
        cudaEventCreateWithFlags(&evB, cudaEventDisableTiming);
    }

    // fork s2 from the main (captured) stream
    cudaEventRecord(evFork, 0);
    cudaStreamWaitEvent(s2, evFork, 0);

    // s2: bucket build (tiny; overlaps compute_W + GEMM-A)
    zero_cnt_kernel<<<(3 * MAXN + 255) / 256, 256, 0, s2>>>();
    place_kernel<<<min((ET + 255) / 256, 8192), 256, 0, s2>>>(e_AB, E_AB, e_BA, E_BA, e_AA, E_AA);
    cudaEventRecord(evPlace, s2);

    // s0: W fragments, then GEMM-A (types 0 and 2 share softmax(logits_A))
    compute_W_kernel<<<(3 * D * D + 255) / 256, 256>>>(Wp_AB, Wn_AB, Wp_BA, Wn_BA, Wp_AA, Wn_AA);
    hmma_gemm_kernel<<<(NA + 63) / 64, 256>>>(logits_A, NA, 0, 2);
    cudaEventRecord(evQA, 0);

    // s2: GEMM-B strictly AFTER GEMM-A; overlaps the two write-gathers on s0
    cudaStreamWaitEvent(s2, evQA, 0);
    hmma_gemm_kernel<<<(NB + 63) / 64, 256, 0, s2>>>(logits_B, NB, 1, -1);
    cudaEventRecord(evB, s2);

    float* dA = out;
    float* dB = out + (size_t)NA * D;

    // s0: write-gathers (need only Q0/Q2 + place) overlap GEMM-B
    cudaStreamWaitEvent(0, evPlace, 0);
    gather_kernel<0, 0><<<(NB * 32 + 255) / 256, 256>>>(dB, NB);   // Q0 -> delta_B
    gather_kernel<2, 0><<<(NA * 32 + 255) / 256, 256>>>(dA, NA);   // Q2 -> delta_A
    // s0: final accumulate pass needs Q1 (GEMM-B)
    cudaStreamWaitEvent(0, evB, 0);
    gather_kernel<1, 1><<<(NA * 32 + 255) / 256, 256>>>(dA, NA);   // Q1 += delta_A
}

// round 15
// speedup vs baseline: 1.1197x; 1.1197x over previous
#include <cuda_runtime.h>
#include <cuda_bf16.h>
#include <cuda_fp16.h>
#include <cstdint>

#define D 128
#define MAXN 100000
#define CAP 64          // bucket capacity per destination (Poisson(10): P(>=64) ~ 1e-18)
#define NDST_MAX 200000

// ---------------- device scratch (allocation-free) ---------------------------
// g_Wfrag[type][kstep(8)][ntile(16)][lane(32)] : uint4 = {b0_hi, b1_hi, b0_lo, b1_lo}
__device__ __align__(16) uint4 g_Wfrag[3][8][16][32];
// Q stored as fp16: halves gather traffic; Q1+Q2+out now fit in L2.
__device__ __half g_Q[3][(size_t)MAXN * D];
__device__ int g_cnt[NDST_MAX];
__device__ unsigned g_bkt[(size_t)NDST_MAX * CAP];

// ---------------- mma.sync helper (sm_80+ path, legal on target sm_103) ------
__device__ __forceinline__ void mma_bf16(float* c, uint32_t a0, uint32_t a1,
                                         uint32_t a2, uint32_t a3,
                                         uint32_t b0, uint32_t b1) {
    asm volatile(
        "mma.sync.aligned.m16n8k16.row.col.f32.bf16.bf16.f32 "
        "{%0,%1,%2,%3}, {%4,%5,%6,%7}, {%8,%9}, {%0,%1,%2,%3};"
        : "+f"(c[0]), "+f"(c[1]), "+f"(c[2]), "+f"(c[3])
        : "r"(a0), "r"(a1), "r"(a2), "r"(a3), "r"(b0), "r"(b1));
}

// ---------------- kernel 0: W = W_pos - softplus(W_negraw), split + frag-pack -
__global__ void compute_W_kernel(const float* __restrict__ wp0, const float* __restrict__ wn0,
                                 const float* __restrict__ wp1, const float* __restrict__ wn1,
                                 const float* __restrict__ wp2, const float* __restrict__ wn2) {
    int i = blockIdx.x * blockDim.x + threadIdx.x;
    if (i >= 3 * D * D) return;
    int ty = i / (D * D), r = i % (D * D);
    int k = r / D, n = r % D;
    const float* wp = (ty == 0) ? wp0 : (ty == 1 ? wp1 : wp2);
    const float* wn = (ty == 0) ? wn0 : (ty == 1 ? wn1 : wn2);
    float x = wn[r];
    float sp = fmaxf(x, 0.0f) + log1pf(expf(-fabsf(x)));
    float w = wp[r] - sp;
    __nv_bfloat16 hb = __float2bfloat16(w);
    __nv_bfloat16 lb = __float2bfloat16(w - __bfloat162float(hb));

    int s  = k >> 4;
    int kk = k & 15;
    int reg  = kk >> 3;
    int tq   = (kk >> 1) & 3;
    int half = kk & 1;
    int j    = n >> 3;
    int lane = (n & 7) * 4 + tq;

    unsigned char* slot = (unsigned char*)&g_Wfrag[ty][s][j][lane];
    *(__nv_bfloat16*)(slot + 0 + reg * 4 + half * 2) = hb;
    *(__nv_bfloat16*)(slot + 8 + reg * 4 + half * 2) = lb;
}

// ---------------- kernel 1: zero destination counts --------------------------
__global__ void zero_cnt_kernel(int ndst) {
    int i = blockIdx.x * blockDim.x + threadIdx.x;
    if (i < ndst) g_cnt[i] = 0;
}

// ---------------- kernel 2: fused softmax + split-bf16 HMMA GEMM -------------
// Block = 256 threads (8 warps), 64 rows/CTA; warp -> (mtile, N-half).
// W fragments staged through an 8KB smem buffer per k-step (cooperative
// LDG->STS, register-prefetch of next step overlapped with MMAs).
// Static smem: P 34KB + Wbuf 8KB = 42KB -> 3 CTAs/SM.  (R10-proven config.)
#define PROW 136

__global__ void __launch_bounds__(256, 3)
hmma_gemm_kernel(const float* __restrict__ X, int nrows, int t0, int t1) {
    __shared__ __align__(16) __nv_bfloat16 sph[64 * PROW];
    __shared__ __align__(16) __nv_bfloat16 spl[64 * PROW];
    __shared__ __align__(16) uint4 sWb[512];          // 16 j x 32 lanes, one k-step

    const int tid  = threadIdx.x;
    const int lane = tid & 31;
    const int warp = tid >> 5;
    const int row0 = blockIdx.x * 64;

    // ---- softmax: 8 warps x 8 rows each; lane owns 4 cols of its row
    #pragma unroll
    for (int r = 0; r < 8; r++) {
        int lrow = warp * 8 + r;
        int row  = row0 + lrow;
        if (row < nrows) {
            const float* xr = X + (size_t)row * D;
            float v[4];
            #pragma unroll
            for (int q = 0; q < 4; q++) v[q] = xr[lane + 32 * q];
            float m = fmaxf(fmaxf(v[0], v[1]), fmaxf(v[2], v[3]));
            #pragma unroll
            for (int o = 16; o > 0; o >>= 1) m = fmaxf(m, __shfl_xor_sync(0xffffffffu, m, o));
            float s = 0.f;
            #pragma unroll
            for (int q = 0; q < 4; q++) { v[q] = expf(v[q] - m); s += v[q]; }
            #pragma unroll
            for (int o = 16; o > 0; o >>= 1) s += __shfl_xor_sync(0xffffffffu, s, o);
            float inv = 1.0f / s;
            #pragma unroll
            for (int q = 0; q < 4; q++) {
                float p = v[q] * inv;
                __nv_bfloat16 hb = __float2bfloat16(p);
                __nv_bfloat16 lb = __float2bfloat16(p - __bfloat162float(hb));
                int col = lane + 32 * q;
                sph[lrow * PROW + col] = hb;
                spl[lrow * PROW + col] = lb;
            }
        } else {
            __nv_bfloat16 z = __float2bfloat16(0.f);
            #pragma unroll
            for (int q = 0; q < 4; q++) {
                int col = lane + 32 * q;
                sph[lrow * PROW + col] = z;
                spl[lrow * PROW + col] = z;
            }
        }
    }
    __syncthreads();

    const int mt = warp >> 1;
    const int nh = warp & 1;
    const int g  = lane >> 2;
    const int tq = lane & 3;

    const uint32_t* ph32 = (const uint32_t*)sph;
    const uint32_t* pl32 = (const uint32_t*)spl;
    const int rbase = (mt * 16 + g) * (PROW / 2);
    const uint4* bs = &sWb[(8 * nh) * 32 + lane];

    const int ntypes = (t1 >= 0) ? 2 : 1;
    for (int tt = 0; tt < ntypes; tt++) {
        const int ty = tt ? t1 : t0;
        const uint4* wt = &g_Wfrag[ty][0][0][0];

        float acc[32];
        #pragma unroll
        for (int i = 0; i < 32; i++) acc[i] = 0.f;

        // prefetch k-step 0 (2 x LDG.128 per thread; 8KB block is contiguous)
        uint4 p0 = wt[tid], p1 = wt[tid + 256];

        #pragma unroll
        for (int s = 0; s < 8; s++) {
            // stage current k-step into smem
            sWb[tid] = p0;
            sWb[tid + 256] = p1;
            __syncthreads();
            // prefetch next k-step; LDG latency hides under the 24 MMAs below
            if (s < 7) { p0 = wt[(s + 1) * 512 + tid]; p1 = wt[(s + 1) * 512 + tid + 256]; }

            const int o = rbase + 8 * s + tq;
            uint32_t ah0 = ph32[o],           ah2 = ph32[o + 4];
            uint32_t ah1 = ph32[o + 8 * 68],  ah3 = ph32[o + 4 + 8 * 68];
            uint32_t al0 = pl32[o],           al2 = pl32[o + 4];
            uint32_t al1 = pl32[o + 8 * 68],  al3 = pl32[o + 4 + 8 * 68];
            #pragma unroll
            for (int j = 0; j < 8; j++) {
                uint4 b = bs[j * 32];                      // LDS.128, conflict-free
                mma_bf16(acc + 4 * j, ah0, ah1, ah2, ah3, b.x, b.y);   // Ph @ Wh
                mma_bf16(acc + 4 * j, al0, al1, al2, al3, b.x, b.y);   // Pl @ Wh
                mma_bf16(acc + 4 * j, ah0, ah1, ah2, ah3, b.z, b.w);   // Ph @ Wl
            }
            __syncthreads();   // all reads of sWb done before next store
        }

        // ---- epilogue: fp16 Q stores (half2 per pair; 4-byte aligned)
        __half* Q = g_Q[ty];
        const int rowa = row0 + mt * 16 + g;
        const int rowb = rowa + 8;
        #pragma unroll
        for (int j = 0; j < 8; j++) {
            int cn = 64 * nh + 8 * j + 2 * tq;
            if (rowa < nrows)
                *(__half2*)(Q + (size_t)rowa * D + cn) = __floats2half2_rn(acc[4 * j], acc[4 * j + 1]);
            if (rowb < nrows)
                *(__half2*)(Q + (size_t)rowb * D + cn) = __floats2half2_rn(acc[4 * j + 2], acc[4 * j + 3]);
        }
    }
}

// ---------------- kernel 3: edge placement into per-dst buckets --------------
// slot value: src | (q << 20)  (src < 2^20, q in {0,1,2})
// global dst: A rows [0,NA), B rows [NA, NA+NB)
__global__ void place_kernel(const int* __restrict__ e0, int E0,   // AB: dst B, Q0
                             const int* __restrict__ e1, int E1,   // BA: dst A, Q1
                             const int* __restrict__ e2, int E2,   // AA: dst A, Q2
                             int NA) {
    int i = blockIdx.x * blockDim.x + threadIdx.x;
    int stride = gridDim.x * blockDim.x;
    int ET = E0 + E1 + E2;
    for (int e = i; e < ET; e += stride) {
        int src, gdst; unsigned q;
        if (e < E0)            { src = e0[e];           gdst = NA + e0[E0 + e];      q = 0; }
        else if (e < E0 + E1)  { int le = e - E0;       src = e1[le]; gdst = e1[E1 + le]; q = 1; }
        else                   { int le = e - E0 - E1;  src = e2[le]; gdst = e2[E2 + le]; q = 2; }
        int pos = atomicAdd(&g_cnt[gdst], 1);
        if (pos < CAP) g_bkt[(size_t)gdst * CAP + pos] = (unsigned)src | (q << 20);
    }
}

// ---------------- kernel 4: per-dst gather + register accumulate -------------
// warp per destination row in [base, base+ndst); writes each output row once.
// Q rows are fp16: lane reads 4 halves (uint2, 8B) -> 256B per row per warp.
__global__ void __launch_bounds__(256)
gather_kernel(float* __restrict__ out, int base, int ndst) {
    int gw   = base + ((blockIdx.x * blockDim.x + threadIdx.x) >> 5);
    int lane = threadIdx.x & 31;
    if (gw >= base + ndst) return;

    int cnt = g_cnt[gw];
    cnt = min(cnt, CAP);
    const unsigned* bk = g_bkt + (size_t)gw * CAP;
    const __half* Qf = &g_Q[0][0];

    float4 acc = make_float4(0.f, 0.f, 0.f, 0.f);

    int n1 = min(cnt, 32);
    unsigned pk = (lane < n1) ? bk[lane] : 0u;
    for (int e = 0; e < n1; e++) {
        unsigned p = __shfl_sync(0xffffffffu, pk, e);
        const uint2* Qr = (const uint2*)(Qf + (size_t)(p >> 20) * ((size_t)MAXN * D)
                                            + (size_t)(p & 0xFFFFFu) * D) + lane;
        uint2 raw = __ldg(Qr);
        float2 v0 = __half22float2(*(const __half2*)&raw.x);
        float2 v1 = __half22float2(*(const __half2*)&raw.y);
        acc.x += v0.x; acc.y += v0.y; acc.z += v1.x; acc.w += v1.y;
    }
    if (cnt > 32) {
        int n2 = cnt - 32;
        unsigned pk2 = (lane < n2) ? bk[32 + lane] : 0u;
        for (int e = 0; e < n2; e++) {
            unsigned p = __shfl_sync(0xffffffffu, pk2, e);
            const uint2* Qr = (const uint2*)(Qf + (size_t)(p >> 20) * ((size_t)MAXN * D)
                                                + (size_t)(p & 0xFFFFFu) * D) + lane;
            uint2 raw = __ldg(Qr);
            float2 v0 = __half22float2(*(const __half2*)&raw.x);
            float2 v1 = __half22float2(*(const __half2*)&raw.y);
            acc.x += v0.x; acc.y += v0.y; acc.z += v1.x; acc.w += v1.y;
        }
    }

    *(float4*)(out + (size_t)gw * D + 4 * lane) = acc;
}

// ---------------- launch -----------------------------------------------------
// Two-stream schedule (R13-proven), GEMMs serialized, GEMM-B ∥ gather-B:
//   s0: compute_W -> GEMM-A -> [wait place] gather-B -> [wait GEMM-B] gather-A
//   s2: [fork] zero_cnt -> place ; [wait GEMM-A] GEMM-B
extern "C" void kernel_launch(void* const* d_in, const int* in_sizes, int n_in,
                              void* d_out, int out_size) {
    const float* logits_A = (const float*)d_in[0];
    const float* logits_B = (const float*)d_in[1];
    const int* e_AB = (const int*)d_in[4];
    const int* e_BA = (const int*)d_in[5];
    const int* e_AA = (const int*)d_in[6];
    const float* Wp_AB = (const float*)d_in[7],  *Wn_AB = (const float*)d_in[8];
    const float* Wp_BA = (const float*)d_in[9],  *Wn_BA = (const float*)d_in[10];
    const float* Wp_AA = (const float*)d_in[11], *Wn_AA = (const float*)d_in[12];
    float* out = (float*)d_out;

    const int NA = in_sizes[0] / D;
    const int NB = in_sizes[1] / D;
    const int E_AB = in_sizes[4] / 2;
    const int E_BA = in_sizes[5] / 2;
    const int E_AA = in_sizes[6] / 2;
    const int NDST = NA + NB;
    const int ET = E_AB + E_BA + E_AA;

    static cudaStream_t s2 = nullptr;
    static cudaEvent_t evFork = nullptr, evPlace = nullptr, evQA = nullptr, evB = nullptr;
    if (s2 == nullptr) {
        cudaStreamCreateWithFlags(&s2, cudaStreamNonBlocking);
        cudaEventCreateWithFlags(&evFork, cudaEventDisableTiming);
        cudaEventCreateWithFlags(&evPlace, cudaEventDisableTiming);
        cudaEventCreateWithFlags(&evQA, cudaEventDisableTiming);
        cudaEventCreateWithFlags(&evB, cudaEventDisableTiming);
    }

    // fork s2 from the main (captured) stream
    cudaEventRecord(evFork, 0);
    cudaStreamWaitEvent(s2, evFork, 0);

    // s2: bucket build (tiny; overlaps compute_W + GEMM-A)
    zero_cnt_kernel<<<(NDST + 255) / 256, 256, 0, s2>>>(NDST);
    place_kernel<<<min((ET + 255) / 256, 8192), 256, 0, s2>>>(e_AB, E_AB, e_BA, E_BA, e_AA, E_AA, NA);
    cudaEventRecord(evPlace, s2);

    // s0: W fragments, then GEMM-A (types 0 and 2 share softmax(logits_A))
    compute_W_kernel<<<(3 * D * D + 255) / 256, 256>>>(Wp_AB, Wn_AB, Wp_BA, Wn_BA, Wp_AA, Wn_AA);
    hmma_gemm_kernel<<<(NA + 63) / 64, 256>>>(logits_A, NA, 0, 2);
    cudaEventRecord(evQA, 0);

    // s2: GEMM-B strictly AFTER GEMM-A; overlaps gather-B below
    cudaStreamWaitEvent(s2, evQA, 0);
    hmma_gemm_kernel<<<(NB + 63) / 64, 256, 0, s2>>>(logits_B, NB, 1, -1);
    cudaEventRecord(evB, s2);

    // s0: gather-B (needs Q0 + place) overlaps GEMM-B; then join and gather-A
    cudaStreamWaitEvent(0, evPlace, 0);
    gather_kernel<<<(NB * 32 + 255) / 256, 256>>>(out, NA, NB);
    cudaStreamWaitEvent(0, evB, 0);     // join s2
    gather_kernel<<<(NA * 32 + 255) / 256, 256>>>(out, 0, NA);
}